// round 6
// baseline (speedup 1.0000x reference)
#include <cuda_runtime.h>

// Ragged segment mean, begin-relative even-split chunking:
//   seq:   [B=2048, L=512, D=512] fp32   (d_in[0])
//   begin: [B] int32                      (d_in[1])
//   end:   [B] int32                      (d_in[2])
//   out:   [B, D] fp32 = mean(seq[b, begin[b]:end[b], :], axis=0)
//
// Kernel 1 zeroes out. Kernel 2: grid (B, 4); chunk c of batch b covers
// rows [begin + len*c/4, begin + len*(c+1)/4) — every CTA has work
// (<=64 rows), no fixed-grid empties. Partial sums are pre-scaled by
// 1/len and reduced into out with a single red.global.add.v4.f32.

#define B_DIM   2048
#define L_DIM   512
#define D_DIM   512
#define THREADS 128          // D_DIM / 4 lanes of float4
#define NSPLIT  4

__global__ __launch_bounds__(THREADS)
void zero_out_kernel(float4* __restrict__ out) {
    out[(size_t)blockIdx.x * THREADS + threadIdx.x] =
        make_float4(0.f, 0.f, 0.f, 0.f);
}

__global__ __launch_bounds__(THREADS)
void ragged_mean_chunk_kernel(const float* __restrict__ seq,
                              const int* __restrict__ begin,
                              const int* __restrict__ end,
                              float* __restrict__ out) {
    const int b = blockIdx.x;
    const int c = blockIdx.y;
    const int t = threadIdx.x;  // owns columns [4t, 4t+4)

    const int sb  = begin[b];
    const int eb  = end[b];
    const int len = eb - sb;    // in [1, 256]

    // Even split of [sb, eb) into NSPLIT pieces (len <= 256, no overflow)
    const int s = sb + (len * c) / NSPLIT;
    const int e = sb + (len * (c + 1)) / NSPLIT;
    if (s >= e) return;         // only when len < NSPLIT

    const float4* base =
        reinterpret_cast<const float4*>(seq + (size_t)b * L_DIM * D_DIM) + t;

    float ax = 0.f, ay = 0.f, az = 0.f, aw = 0.f;

    int l = s;
    for (; l + 4 <= e; l += 4) {
        float4 v0 = __ldcs(&base[(size_t)(l + 0) * (D_DIM / 4)]);
        float4 v1 = __ldcs(&base[(size_t)(l + 1) * (D_DIM / 4)]);
        float4 v2 = __ldcs(&base[(size_t)(l + 2) * (D_DIM / 4)]);
        float4 v3 = __ldcs(&base[(size_t)(l + 3) * (D_DIM / 4)]);
        ax += v0.x + v1.x + v2.x + v3.x;
        ay += v0.y + v1.y + v2.y + v3.y;
        az += v0.z + v1.z + v2.z + v3.z;
        aw += v0.w + v1.w + v2.w + v3.w;
    }
    for (; l < e; ++l) {
        float4 v = __ldcs(&base[(size_t)l * (D_DIM / 4)]);
        ax += v.x; ay += v.y; az += v.z; aw += v.w;
    }

    const float inv = 1.0f / (float)len;
    ax *= inv; ay *= inv; az *= inv; aw *= inv;

    float* dst = out + (size_t)b * D_DIM + 4 * t;  // 16B aligned
    // Single vector reduction (REDG.128, no return) instead of 4 scalar REDG
    asm volatile("red.global.add.v4.f32 [%0], {%1, %2, %3, %4};"
                 :: "l"(dst), "f"(ax), "f"(ay), "f"(az), "f"(aw)
                 : "memory");
}

extern "C" void kernel_launch(void* const* d_in, const int* in_sizes, int n_in,
                              void* d_out, int out_size) {
    const float* seq   = (const float*)d_in[0];
    const int*   begin = (const int*)d_in[1];
    const int*   end   = (const int*)d_in[2];
    float*       out   = (float*)d_out;

    zero_out_kernel<<<B_DIM, THREADS>>>((float4*)out);

    dim3 grid(B_DIM, NSPLIT);
    ragged_mean_chunk_kernel<<<grid, THREADS>>>(seq, begin, end, out);
}

// round 7
// speedup vs baseline: 1.0709x; 1.0709x over previous
#include <cuda_runtime.h>

// Ragged segment mean, begin-relative even-split (NSPLIT=8):
//   seq:   [B=2048, L=512, D=512] fp32   (d_in[0])
//   begin: [B] int32                      (d_in[1])
//   end:   [B] int32                      (d_in[2])
//   out:   [B, D] fp32 = mean(seq[b, begin[b]:end[b], :], axis=0)
//
// cudaMemsetAsync zeroes out (graph-capturable, no kernel launch).
// Main kernel: grid (B, 8); chunk c of batch b covers rows
// [begin + len*c/8, begin + len*(c+1)/8) — every CTA has <=32 rows,
// zero empty CTAs, balance granule 64KB. Partials pre-scaled by 1/len
// and merged with one red.global.add.v4.f32 per thread.

#define B_DIM   2048
#define L_DIM   512
#define D_DIM   512
#define THREADS 128          // D_DIM / 4 lanes of float4
#define NSPLIT  8

__global__ __launch_bounds__(THREADS)
void ragged_mean_chunk_kernel(const float* __restrict__ seq,
                              const int* __restrict__ begin,
                              const int* __restrict__ end,
                              float* __restrict__ out) {
    const int b = blockIdx.x;
    const int c = blockIdx.y;
    const int t = threadIdx.x;  // owns columns [4t, 4t+4)

    const int sb  = begin[b];
    const int eb  = end[b];
    const int len = eb - sb;    // in [1, 256]

    // Even split of [sb, eb) into NSPLIT pieces (len <= 256, no overflow)
    const int s = sb + (len * c) / NSPLIT;
    const int e = sb + (len * (c + 1)) / NSPLIT;
    if (s >= e) return;         // only when len < NSPLIT

    const float4* base =
        reinterpret_cast<const float4*>(seq + (size_t)b * L_DIM * D_DIM) + t;

    float ax = 0.f, ay = 0.f, az = 0.f, aw = 0.f;

    int l = s;
    for (; l + 4 <= e; l += 4) {
        float4 v0 = __ldcs(&base[(size_t)(l + 0) * (D_DIM / 4)]);
        float4 v1 = __ldcs(&base[(size_t)(l + 1) * (D_DIM / 4)]);
        float4 v2 = __ldcs(&base[(size_t)(l + 2) * (D_DIM / 4)]);
        float4 v3 = __ldcs(&base[(size_t)(l + 3) * (D_DIM / 4)]);
        ax += v0.x + v1.x + v2.x + v3.x;
        ay += v0.y + v1.y + v2.y + v3.y;
        az += v0.z + v1.z + v2.z + v3.z;
        aw += v0.w + v1.w + v2.w + v3.w;
    }
    for (; l < e; ++l) {
        float4 v = __ldcs(&base[(size_t)l * (D_DIM / 4)]);
        ax += v.x; ay += v.y; az += v.z; aw += v.w;
    }

    const float inv = 1.0f / (float)len;
    ax *= inv; ay *= inv; az *= inv; aw *= inv;

    float* dst = out + (size_t)b * D_DIM + 4 * t;  // 16B aligned
    asm volatile("red.global.add.v4.f32 [%0], {%1, %2, %3, %4};"
                 :: "l"(dst), "f"(ax), "f"(ay), "f"(az), "f"(aw)
                 : "memory");
}

extern "C" void kernel_launch(void* const* d_in, const int* in_sizes, int n_in,
                              void* d_out, int out_size) {
    const float* seq   = (const float*)d_in[0];
    const int*   begin = (const int*)d_in[1];
    const int*   end   = (const int*)d_in[2];
    float*       out   = (float*)d_out;

    // Zero the accumulation target (async, graph-capturable)
    cudaMemsetAsync(d_out, 0, (size_t)B_DIM * D_DIM * sizeof(float));

    dim3 grid(B_DIM, NSPLIT);
    ragged_mean_chunk_kernel<<<grid, THREADS>>>(seq, begin, end, out);
}